// round 2
// baseline (speedup 1.0000x reference)
#include <cuda_runtime.h>
#include <cuda_bf16.h>
#include <math.h>

#define L_SEQ   2048
#define BATCH   64
#define EMB     256
#define HID     128
#define G4      512
#define NUTT    128
#define SEP_TOK 50256
#define MTOT    (NUTT * BATCH)   // 8192

// ---------------- device scratch ----------------
__device__ int   g_seg[L_SEQ * BATCH];
__device__ int   g_ustart[(NUTT + 1) * BATCH];
__device__ float g_u[MTOT * EMB];                 // [t*64+b][256]
__device__ float g_xp[2ull * MTOT * G4];          // [dir][t*64+b][512]
__device__ float g_h[2ull * MTOT * HID];          // [dir][t][b][128]
__device__ int   g_umask[MTOT];

__device__ __forceinline__ float sigf(float v) { return 1.0f / (1.0f + expf(-v)); }

// ---------------- K1: segment ids + utterance starts ----------------
__global__ void k1_seg(const int* __restrict__ x) {
    int b = blockIdx.x, tid = threadIdx.x;
    __shared__ int cnt[256];
    for (int i = tid; i <= NUTT; i += 256) g_ustart[i * BATCH + b] = L_SEQ;
    int base = tid * 8;
    int loc[8]; int c = 0;
    #pragma unroll
    for (int k = 0; k < 8; k++) {
        loc[k] = (x[(base + k) * BATCH + b] == SEP_TOK) ? 1 : 0;
        c += loc[k];
    }
    cnt[tid] = c;
    __syncthreads();
    for (int off = 1; off < 256; off <<= 1) {
        int v = (tid >= off) ? cnt[tid - off] : 0;
        __syncthreads();
        cnt[tid] += v;
        __syncthreads();
    }
    int run = (tid > 0) ? cnt[tid - 1] : 0;   // seps strictly before base
    #pragma unroll
    for (int k = 0; k < 8; k++) {
        int t = base + k;
        g_seg[t * BATCH + b] = run;
        if (loc[k]) {
            if (run + 1 <= NUTT) g_ustart[(run + 1) * BATCH + b] = t + 1;
            run++;
        }
    }
    if (tid == 0) g_ustart[b] = 0;
}

// ---------------- K2: ragged mean-pool ----------------
__global__ void k2_pool(const int* __restrict__ x, const float* __restrict__ emb) {
    int uu = blockIdx.x, b = blockIdx.y;
    __shared__ int rows[L_SEQ];
    __shared__ int se[2];
    if (threadIdx.x < 2)
        se[threadIdx.x] = g_ustart[(uu + threadIdx.x) * BATCH + b];
    __syncthreads();
    int s = se[0], e = se[1];
    for (int t = s + threadIdx.x; t < e; t += 256) rows[t - s] = x[t * BATCH + b];
    __syncthreads();
    int n = e - s;
    float sum = 0.f;
    for (int i = 0; i < n; i++)
        sum += emb[(size_t)rows[i] * EMB + threadIdx.x];
    g_u[((size_t)uu * BATCH + b) * EMB + threadIdx.x] = (n > 0) ? sum / (float)n : 0.f;
}

// ---------------- K3: xp = U @ Wcat^T + biases (fp32) ----------------
#define BM 128
#define BN 128
#define BKK 16
__global__ void __launch_bounds__(256) k3_gemm(
    const float* __restrict__ wihf, const float* __restrict__ wihb,
    const float* __restrict__ bihf, const float* __restrict__ bhhf,
    const float* __restrict__ bihb, const float* __restrict__ bhhb) {
    __shared__ float As[BKK][BM + 4];
    __shared__ float Bs[BKK][BN + 4];
    int m0 = blockIdx.x * BM, n0 = blockIdx.y * BN;
    int tid = threadIdx.x;
    int tx = tid & 15, ty = tid >> 4;
    float acc[8][8];
    #pragma unroll
    for (int i = 0; i < 8; i++)
        #pragma unroll
        for (int j = 0; j < 8; j++) acc[i][j] = 0.f;

    for (int k0 = 0; k0 < EMB; k0 += BKK) {
        #pragma unroll
        for (int i = 0; i < 2; i++) {
            int t2 = tid * 2 + i;
            int r  = t2 >> 2;
            int c4 = (t2 & 3) * 4;
            float4 v = *(const float4*)&g_u[((size_t)(m0 + r)) * EMB + k0 + c4];
            As[c4 + 0][r] = v.x; As[c4 + 1][r] = v.y;
            As[c4 + 2][r] = v.z; As[c4 + 3][r] = v.w;
            int n = n0 + r;
            const float* bs = (n < G4) ? &wihf[(size_t)n * EMB] : &wihb[(size_t)(n - G4) * EMB];
            float4 w = *(const float4*)&bs[k0 + c4];
            Bs[c4 + 0][r] = w.x; Bs[c4 + 1][r] = w.y;
            Bs[c4 + 2][r] = w.z; Bs[c4 + 3][r] = w.w;
        }
        __syncthreads();
        #pragma unroll
        for (int kk = 0; kk < BKK; kk++) {
            float a[8], bb[8];
            #pragma unroll
            for (int i = 0; i < 8; i++) a[i]  = As[kk][ty * 8 + i];
            #pragma unroll
            for (int j = 0; j < 8; j++) bb[j] = Bs[kk][tx * 8 + j];
            #pragma unroll
            for (int i = 0; i < 8; i++)
                #pragma unroll
                for (int j = 0; j < 8; j++) acc[i][j] += a[i] * bb[j];
        }
        __syncthreads();
    }
    #pragma unroll
    for (int i = 0; i < 8; i++) {
        int m = m0 + ty * 8 + i;
        #pragma unroll
        for (int j = 0; j < 8; j++) {
            int n   = n0 + tx * 8 + j;
            int dir = n >> 9;
            int gi  = n & (G4 - 1);
            float bias = dir ? (bihb[gi] + bhhb[gi]) : (bihf[gi] + bhhf[gi]);
            g_xp[((size_t)dir * MTOT + m) * G4 + gi] = acc[i][j] + bias;
        }
    }
}

// ---------------- K4: persistent BiLSTM ----------------
// 128 blocks = (dir, batch), 256 threads. Thread tid computes gate rows tid
// (i/f, weights in smem transposed stride 257) and tid+256 (g/o, 128 regs).
#define WS_S   257
#define SM_WS  (HID * WS_S)          // 32896 floats
#define SM_G4  SM_WS                 // +512
#define SM_H   (SM_G4 + 512)         // +128
#define K4_SMEM_BYTES ((SM_H + 128) * 4)

__global__ void __launch_bounds__(256, 1) k4_lstm(
    const float* __restrict__ whhf, const float* __restrict__ whhb) {
    extern __shared__ float sm[];
    float* ws  = sm;
    float* gsm = sm + SM_G4;
    float* hsm = sm + SM_H;

    int bi = blockIdx.x;
    int dir = bi >> 6, b = bi & 63;
    const float* whh = dir ? whhb : whhf;
    int tid = threadIdx.x;

    // rows 0..255 (i,f) -> smem transposed: ws[j*257 + row]
    for (int idx4 = tid; idx4 < (256 * HID) / 4; idx4 += 256) {
        int row = idx4 >> 5;
        int j0  = (idx4 & 31) * 4;
        float4 v = ((const float4*)whh)[idx4];
        ws[(j0 + 0) * WS_S + row] = v.x;
        ws[(j0 + 1) * WS_S + row] = v.y;
        ws[(j0 + 2) * WS_S + row] = v.z;
        ws[(j0 + 3) * WS_S + row] = v.w;
    }
    // row 256+tid (g/o) -> registers
    float wreg[HID];
    {
        const float4* wr = (const float4*)(whh + (size_t)(256 + tid) * HID);
        #pragma unroll
        for (int q = 0; q < 32; q++) {
            float4 v = wr[q];
            wreg[4 * q + 0] = v.x; wreg[4 * q + 1] = v.y;
            wreg[4 * q + 2] = v.z; wreg[4 * q + 3] = v.w;
        }
    }
    if (tid < HID) hsm[tid] = 0.f;
    float c = 0.f;
    __syncthreads();

    #pragma unroll 1
    for (int s = 0; s < NUTT; s++) {
        int t = dir ? (NUTT - 1 - s) : s;
        size_t base = ((size_t)dir * MTOT + (size_t)t * BATCH + b) * G4;
        float xpA = g_xp[base + tid];
        float xpB = g_xp[base + 256 + tid];
        float accA = 0.f, accB = 0.f;
        #pragma unroll
        for (int j0 = 0; j0 < HID; j0 += 32) {
            float4 hc[8];
            #pragma unroll
            for (int u = 0; u < 8; u++) hc[u] = *(const float4*)&hsm[j0 + 4 * u];
            #pragma unroll
            for (int u = 0; u < 8; u++) {
                int j = j0 + 4 * u;
                accA += ws[(j + 0) * WS_S + tid] * hc[u].x;
                accA += ws[(j + 1) * WS_S + tid] * hc[u].y;
                accA += ws[(j + 2) * WS_S + tid] * hc[u].z;
                accA += ws[(j + 3) * WS_S + tid] * hc[u].w;
                accB += wreg[j + 0] * hc[u].x;
                accB += wreg[j + 1] * hc[u].y;
                accB += wreg[j + 2] * hc[u].z;
                accB += wreg[j + 3] * hc[u].w;
            }
        }
        gsm[tid]       = accA + xpA;
        gsm[256 + tid] = accB + xpB;
        __syncthreads();
        if (tid < HID) {
            float gi = gsm[tid], gf = gsm[HID + tid];
            float gg = gsm[256 + tid], go = gsm[384 + tid];
            c = sigf(gf) * c + sigf(gi) * tanhf(gg);
            float h = sigf(go) * tanhf(c);
            hsm[tid] = h;
            g_h[(((size_t)dir * NUTT + t) * BATCH + b) * HID + tid] = h;
        }
        __syncthreads();
    }
}

// ---------------- K5: head (logits/softmax/argmax) ----------------
__global__ void k5_head(const float* __restrict__ wout, const float* __restrict__ bout,
                        float* __restrict__ out) {
    int idx = blockIdx.x * blockDim.x + threadIdx.x;   // t*64+b
    if (idx >= MTOT) return;
    int t = idx >> 6, b = idx & 63;
    const float* hf = &g_h[(((size_t)0 * NUTT + t) * BATCH + b) * HID];
    const float* hb = &g_h[(((size_t)1 * NUTT + t) * BATCH + b) * HID];
    float l0 = bout[0], l1 = bout[1];
    for (int e = 0; e < HID; e++) {
        float v = hf[e];
        l0 += v * wout[e];
        l1 += v * wout[EMB + e];
    }
    for (int e = 0; e < HID; e++) {
        float v = hb[e];
        l0 += v * wout[HID + e];
        l1 += v * wout[EMB + HID + e];
    }
    float m  = fmaxf(l0, l1);
    float e0 = expf(l0 - m), e1 = expf(l1 - m);
    float s  = e0 + e1;
    float p0 = e0 / s, p1 = e1 / s;
    int am = (l1 > l0) ? 1 : 0;
    out[idx * 2 + 0]          = l0;
    out[idx * 2 + 1]          = l1;
    out[16384 + idx * 2 + 0]  = p0;
    out[16384 + idx * 2 + 1]  = p1;
    out[32768 + idx]          = am ? p1 : p0;
    out[40960 + idx]          = (float)am;
    g_umask[idx]              = am;
}

// ---------------- K6: expand mask to tokens ----------------
__global__ void k6_mask(const int* __restrict__ x, float* __restrict__ out) {
    int i = blockIdx.x * blockDim.x + threadIdx.x;   // t*B+b
    if (i >= L_SEQ * BATCH) return;
    int b   = i & 63;
    int seg = g_seg[i];
    int m   = g_umask[seg * BATCH + b];
    out[49152 + i] = m ? (float)x[i] : 0.0f;
}

extern "C" void kernel_launch(void* const* d_in, const int* in_sizes, int n_in,
                              void* d_out, int out_size) {
    const int*   x    = (const int*)d_in[0];
    const float* emb  = (const float*)d_in[1];
    const float* wihf = (const float*)d_in[2];
    const float* whhf = (const float*)d_in[3];
    const float* bihf = (const float*)d_in[4];
    const float* bhhf = (const float*)d_in[5];
    const float* wihb = (const float*)d_in[6];
    const float* whhb = (const float*)d_in[7];
    const float* bihb = (const float*)d_in[8];
    const float* bhhb = (const float*)d_in[9];
    const float* wout = (const float*)d_in[10];
    const float* bout = (const float*)d_in[11];
    float* out = (float*)d_out;

    cudaFuncSetAttribute(k4_lstm, cudaFuncAttributeMaxDynamicSharedMemorySize, K4_SMEM_BYTES);

    k1_seg <<<BATCH, 256>>>(x);
    k2_pool<<<dim3(NUTT, BATCH), 256>>>(x, emb);
    k3_gemm<<<dim3(MTOT / BM, (2 * G4) / BN), 256>>>(wihf, wihb, bihf, bhhf, bihb, bhhb);
    k4_lstm<<<2 * BATCH, 256, K4_SMEM_BYTES>>>(whhf, whhb);
    k5_head<<<MTOT / 256, 256>>>(wout, bout, out);
    k6_mask<<<(L_SEQ * BATCH) / 256, 256>>>(x, out);
}

// round 4
// speedup vs baseline: 1.2197x; 1.2197x over previous
#include <cuda_runtime.h>
#include <cuda_bf16.h>
#include <math.h>

#define L_SEQ   2048
#define BATCH   64
#define EMB     256
#define HID     128
#define G4      512
#define NUTT    128
#define SEP_TOK 50256
#define MTOT    (NUTT * BATCH)   // 8192

// ---------------- device scratch ----------------
__device__ int   g_seg[L_SEQ * BATCH];
__device__ int   g_ustart[(NUTT + 1) * BATCH];
__device__ float g_u[MTOT * EMB];                 // [t*64+b][256]
__device__ float g_xp[2ull * MTOT * G4];          // [dir][t*64+b][512]
__device__ float g_h[2ull * MTOT * HID];          // [dir][t][b][128]
__device__ int   g_umask[MTOT];

__device__ __forceinline__ float sigf(float v) { return 1.0f / (1.0f + expf(-v)); }

// ---------------- K1: segment ids + utterance starts ----------------
__global__ void k1_seg(const int* __restrict__ x) {
    int b = blockIdx.x, tid = threadIdx.x;
    __shared__ int cnt[256];
    for (int i = tid; i <= NUTT; i += 256) g_ustart[i * BATCH + b] = L_SEQ;
    int base = tid * 8;
    int loc[8]; int c = 0;
    #pragma unroll
    for (int k = 0; k < 8; k++) {
        loc[k] = (x[(base + k) * BATCH + b] == SEP_TOK) ? 1 : 0;
        c += loc[k];
    }
    cnt[tid] = c;
    __syncthreads();
    for (int off = 1; off < 256; off <<= 1) {
        int v = (tid >= off) ? cnt[tid - off] : 0;
        __syncthreads();
        cnt[tid] += v;
        __syncthreads();
    }
    int run = (tid > 0) ? cnt[tid - 1] : 0;
    #pragma unroll
    for (int k = 0; k < 8; k++) {
        int t = base + k;
        g_seg[t * BATCH + b] = run;
        if (loc[k]) {
            if (run + 1 <= NUTT) g_ustart[(run + 1) * BATCH + b] = t + 1;
            run++;
        }
    }
    if (tid == 0) g_ustart[b] = 0;
}

// ---------------- K2: ragged mean-pool ----------------
__global__ void k2_pool(const int* __restrict__ x, const float* __restrict__ emb) {
    int uu = blockIdx.x, b = blockIdx.y;
    __shared__ int rows[L_SEQ];
    __shared__ int se[2];
    if (threadIdx.x < 2)
        se[threadIdx.x] = g_ustart[(uu + threadIdx.x) * BATCH + b];
    __syncthreads();
    int s = se[0], e = se[1];
    for (int t = s + threadIdx.x; t < e; t += 256) rows[t - s] = x[t * BATCH + b];
    __syncthreads();
    int n = e - s;
    float sum = 0.f;
    for (int i = 0; i < n; i++)
        sum += emb[(size_t)rows[i] * EMB + threadIdx.x];
    g_u[((size_t)uu * BATCH + b) * EMB + threadIdx.x] = (n > 0) ? sum / (float)n : 0.f;
}

// ---------------- K3: xp = U @ Wcat^T + biases (fp32, double-buffered) ----------------
#define BM 128
#define BN 128
#define BKK 16
#define NKT (EMB / BKK)
__global__ void __launch_bounds__(256) k3_gemm(
    const float* __restrict__ wihf, const float* __restrict__ wihb,
    const float* __restrict__ bihf, const float* __restrict__ bhhf,
    const float* __restrict__ bihb, const float* __restrict__ bhhb) {
    __shared__ float As[2][BKK][BM + 4];
    __shared__ float Bs[2][BKK][BN + 4];
    int m0 = blockIdx.x * BM, n0 = blockIdx.y * BN;
    int tid = threadIdx.x;
    int tx = tid & 15, ty = tid >> 4;
    float acc[8][8];
    #pragma unroll
    for (int i = 0; i < 8; i++)
        #pragma unroll
        for (int j = 0; j < 8; j++) acc[i][j] = 0.f;

    int t2a = tid * 2, t2b = tid * 2 + 1;
    int ra = t2a >> 2, ca = (t2a & 3) * 4;
    int rb = t2b >> 2, cb = (t2b & 3) * 4;
    int na = n0 + ra, nb = n0 + rb;
    const float* bpa = (na < G4) ? &wihf[(size_t)na * EMB] : &wihb[(size_t)(na - G4) * EMB];
    const float* bpb = (nb < G4) ? &wihf[(size_t)nb * EMB] : &wihb[(size_t)(nb - G4) * EMB];
    const float* apa = &g_u[(size_t)(m0 + ra) * EMB];
    const float* apb = &g_u[(size_t)(m0 + rb) * EMB];

    float4 av0, av1, bv0, bv1;
    av0 = *(const float4*)&apa[ca];
    av1 = *(const float4*)&apb[cb];
    bv0 = *(const float4*)&bpa[ca];
    bv1 = *(const float4*)&bpb[cb];
    {
        As[0][ca + 0][ra] = av0.x; As[0][ca + 1][ra] = av0.y;
        As[0][ca + 2][ra] = av0.z; As[0][ca + 3][ra] = av0.w;
        As[0][cb + 0][rb] = av1.x; As[0][cb + 1][rb] = av1.y;
        As[0][cb + 2][rb] = av1.z; As[0][cb + 3][rb] = av1.w;
        Bs[0][ca + 0][ra] = bv0.x; Bs[0][ca + 1][ra] = bv0.y;
        Bs[0][ca + 2][ra] = bv0.z; Bs[0][ca + 3][ra] = bv0.w;
        Bs[0][cb + 0][rb] = bv1.x; Bs[0][cb + 1][rb] = bv1.y;
        Bs[0][cb + 2][rb] = bv1.z; Bs[0][cb + 3][rb] = bv1.w;
    }
    __syncthreads();

    #pragma unroll 1
    for (int kt = 0; kt < NKT; kt++) {
        int cur = kt & 1;
        if (kt + 1 < NKT) {
            int k0 = (kt + 1) * BKK;
            av0 = *(const float4*)&apa[k0 + ca];
            av1 = *(const float4*)&apb[k0 + cb];
            bv0 = *(const float4*)&bpa[k0 + ca];
            bv1 = *(const float4*)&bpb[k0 + cb];
        }
        #pragma unroll
        for (int kk = 0; kk < BKK; kk++) {
            float4 a0 = *(const float4*)&As[cur][kk][ty * 8];
            float4 a1 = *(const float4*)&As[cur][kk][ty * 8 + 4];
            float4 b0 = *(const float4*)&Bs[cur][kk][tx * 8];
            float4 b1 = *(const float4*)&Bs[cur][kk][tx * 8 + 4];
            float a[8] = {a0.x, a0.y, a0.z, a0.w, a1.x, a1.y, a1.z, a1.w};
            float bb[8] = {b0.x, b0.y, b0.z, b0.w, b1.x, b1.y, b1.z, b1.w};
            #pragma unroll
            for (int i = 0; i < 8; i++)
                #pragma unroll
                for (int j = 0; j < 8; j++) acc[i][j] += a[i] * bb[j];
        }
        if (kt + 1 < NKT) {
            int nxt = 1 - cur;
            As[nxt][ca + 0][ra] = av0.x; As[nxt][ca + 1][ra] = av0.y;
            As[nxt][ca + 2][ra] = av0.z; As[nxt][ca + 3][ra] = av0.w;
            As[nxt][cb + 0][rb] = av1.x; As[nxt][cb + 1][rb] = av1.y;
            As[nxt][cb + 2][rb] = av1.z; As[nxt][cb + 3][rb] = av1.w;
            Bs[nxt][ca + 0][ra] = bv0.x; Bs[nxt][ca + 1][ra] = bv0.y;
            Bs[nxt][ca + 2][ra] = bv0.z; Bs[nxt][ca + 3][ra] = bv0.w;
            Bs[nxt][cb + 0][rb] = bv1.x; Bs[nxt][cb + 1][rb] = bv1.y;
            Bs[nxt][cb + 2][rb] = bv1.z; Bs[nxt][cb + 3][rb] = bv1.w;
            __syncthreads();
        }
    }
    #pragma unroll
    for (int i = 0; i < 8; i++) {
        int m = m0 + ty * 8 + i;
        #pragma unroll
        for (int j = 0; j < 8; j++) {
            int n   = n0 + tx * 8 + j;
            int dir = n >> 9;
            int gi  = n & (G4 - 1);
            float bias = dir ? (bihb[gi] + bhhb[gi]) : (bihf[gi] + bhhf[gi]);
            g_xp[((size_t)dir * MTOT + m) * G4 + gi] = acc[i][j] + bias;
        }
    }
}

// ---------------- K4: persistent BiLSTM ----------------
#define WS_S   257
#define WS_NJ  64
#define SM_G4  (WS_NJ * WS_S)        // 16448 floats
#define SM_H   (SM_G4 + 512)
#define K4_SMEM_BYTES ((SM_H + 128) * 4)

__global__ void __launch_bounds__(256, 1) k4_lstm(
    const float* __restrict__ whhf, const float* __restrict__ whhb) {
    extern __shared__ float sm[];
    float* ws  = sm;
    float* gsm = sm + SM_G4;
    float* hsm = sm + SM_H;

    int bi = blockIdx.x;
    int dir = bi >> 6, b = bi & 63;
    const float* whh = dir ? whhb : whhf;
    int tid = threadIdx.x;

    for (int idx = tid; idx < 256 * WS_NJ; idx += 256) {
        int row = idx >> 6;
        int j   = idx & 63;
        ws[j * WS_S + row] = whh[row * HID + 64 + j];
    }
    float wregGO[HID];
    {
        const float4* wr = (const float4*)(whh + (size_t)(256 + tid) * HID);
        #pragma unroll
        for (int q = 0; q < 32; q++) {
            float4 v = wr[q];
            wregGO[4 * q + 0] = v.x; wregGO[4 * q + 1] = v.y;
            wregGO[4 * q + 2] = v.z; wregGO[4 * q + 3] = v.w;
        }
    }
    float wregIF[WS_NJ];
    {
        const float4* wr = (const float4*)(whh + (size_t)tid * HID);
        #pragma unroll
        for (int q = 0; q < 16; q++) {
            float4 v = wr[q];
            wregIF[4 * q + 0] = v.x; wregIF[4 * q + 1] = v.y;
            wregIF[4 * q + 2] = v.z; wregIF[4 * q + 3] = v.w;
        }
    }
    if (tid < HID) hsm[tid] = 0.f;
    float c = 0.f;
    __syncthreads();

    int t0 = dir ? (NUTT - 1) : 0;
    size_t base0 = ((size_t)dir * MTOT + (size_t)t0 * BATCH + b) * G4;
    float xpA = g_xp[base0 + tid];
    float xpB = g_xp[base0 + 256 + tid];
    float xpA_n = 0.f, xpB_n = 0.f;

    #pragma unroll 1
    for (int s = 0; s < NUTT; s++) {
        int t = dir ? (NUTT - 1 - s) : s;
        if (s + 1 < NUTT) {
            int tn = dir ? (NUTT - 2 - s) : (s + 1);
            size_t bn = ((size_t)dir * MTOT + (size_t)tn * BATCH + b) * G4;
            xpA_n = g_xp[bn + tid];
            xpB_n = g_xp[bn + 256 + tid];
        }

        float aA0 = 0.f, aA1 = 0.f, aA2 = 0.f, aA3 = 0.f;
        float aB0 = 0.f, aB1 = 0.f, aB2 = 0.f, aB3 = 0.f;
        #pragma unroll
        for (int u = 0; u < 8; u++) {
            int j = 4 * u;
            float4 h4 = *(const float4*)&hsm[j];
            aA0 += wregIF[j + 0] * h4.x + wregIF[j + 1] * h4.y
                 + wregIF[j + 2] * h4.z + wregIF[j + 3] * h4.w;
            aB0 += wregGO[j + 0] * h4.x + wregGO[j + 1] * h4.y
                 + wregGO[j + 2] * h4.z + wregGO[j + 3] * h4.w;
        }
        #pragma unroll
        for (int u = 0; u < 8; u++) {
            int j = 32 + 4 * u;
            float4 h4 = *(const float4*)&hsm[j];
            aA1 += wregIF[j + 0] * h4.x + wregIF[j + 1] * h4.y
                 + wregIF[j + 2] * h4.z + wregIF[j + 3] * h4.w;
            aB1 += wregGO[j + 0] * h4.x + wregGO[j + 1] * h4.y
                 + wregGO[j + 2] * h4.z + wregGO[j + 3] * h4.w;
        }
        #pragma unroll
        for (int u = 0; u < 8; u++) {
            int j = 64 + 4 * u;
            float4 h4 = *(const float4*)&hsm[j];
            int jj = 4 * u;
            aA2 += ws[(jj + 0) * WS_S + tid] * h4.x
                 + ws[(jj + 1) * WS_S + tid] * h4.y
                 + ws[(jj + 2) * WS_S + tid] * h4.z
                 + ws[(jj + 3) * WS_S + tid] * h4.w;
            aB2 += wregGO[j + 0] * h4.x + wregGO[j + 1] * h4.y
                 + wregGO[j + 2] * h4.z + wregGO[j + 3] * h4.w;
        }
        #pragma unroll
        for (int u = 0; u < 8; u++) {
            int j = 96 + 4 * u;
            float4 h4 = *(const float4*)&hsm[j];
            int jj = 32 + 4 * u;
            aA3 += ws[(jj + 0) * WS_S + tid] * h4.x
                 + ws[(jj + 1) * WS_S + tid] * h4.y
                 + ws[(jj + 2) * WS_S + tid] * h4.z
                 + ws[(jj + 3) * WS_S + tid] * h4.w;
            aB3 += wregGO[j + 0] * h4.x + wregGO[j + 1] * h4.y
                 + wregGO[j + 2] * h4.z + wregGO[j + 3] * h4.w;
        }
        gsm[tid]       = (aA0 + aA1) + (aA2 + aA3) + xpA;
        gsm[256 + tid] = (aB0 + aB1) + (aB2 + aB3) + xpB;
        __syncthreads();
        if (tid < HID) {
            float gi = gsm[tid], gf = gsm[HID + tid];
            float gg = gsm[256 + tid], go = gsm[384 + tid];
            c = sigf(gf) * c + sigf(gi) * tanhf(gg);
            float h = sigf(go) * tanhf(c);
            hsm[tid] = h;
            g_h[(((size_t)dir * NUTT + t) * BATCH + b) * HID + tid] = h;
        }
        xpA = xpA_n;
        xpB = xpB_n;
        __syncthreads();
    }
}

// ---------------- K5: head (warp per (t,b)) ----------------
__global__ void k5_head(const float* __restrict__ wout, const float* __restrict__ bout,
                        float* __restrict__ out) {
    int w = threadIdx.x >> 5, lane = threadIdx.x & 31;
    int idx = blockIdx.x * 8 + w;           // t*64+b
    if (idx >= MTOT) return;
    int t = idx >> 6, b = idx & 63;
    const float* hf = &g_h[(((size_t)0 * NUTT + t) * BATCH + b) * HID];
    const float* hb = &g_h[(((size_t)1 * NUTT + t) * BATCH + b) * HID];
    float l0 = 0.f, l1 = 0.f;
    #pragma unroll
    for (int q = 0; q < 4; q++) {
        int e = q * 32 + lane;
        float vf = hf[e], vb = hb[e];
        l0 += vf * wout[e] + vb * wout[HID + e];
        l1 += vf * wout[EMB + e] + vb * wout[EMB + HID + e];
    }
    #pragma unroll
    for (int off = 16; off > 0; off >>= 1) {
        l0 += __shfl_xor_sync(0xFFFFFFFFu, l0, off);
        l1 += __shfl_xor_sync(0xFFFFFFFFu, l1, off);
    }
    if (lane == 0) {
        l0 += bout[0]; l1 += bout[1];
        float m  = fmaxf(l0, l1);
        float e0 = expf(l0 - m), e1 = expf(l1 - m);
        float s  = e0 + e1;
        float p0 = e0 / s, p1 = e1 / s;
        int am = (l1 > l0) ? 1 : 0;
        out[idx * 2 + 0]         = l0;
        out[idx * 2 + 1]         = l1;
        out[16384 + idx * 2 + 0] = p0;
        out[16384 + idx * 2 + 1] = p1;
        out[32768 + idx]         = am ? p1 : p0;
        out[40960 + idx]         = (float)am;
        g_umask[idx]             = am;
    }
}

// ---------------- K6: expand mask to tokens ----------------
__global__ void k6_mask(const int* __restrict__ x, float* __restrict__ out) {
    int i = blockIdx.x * blockDim.x + threadIdx.x;
    if (i >= L_SEQ * BATCH) return;
    int b   = i & 63;
    int seg = g_seg[i];
    int m   = g_umask[seg * BATCH + b];
    out[49152 + i] = m ? (float)x[i] : 0.0f;
}

extern "C" void kernel_launch(void* const* d_in, const int* in_sizes, int n_in,
                              void* d_out, int out_size) {
    const int*   x    = (const int*)d_in[0];
    const float* emb  = (const float*)d_in[1];
    const float* wihf = (const float*)d_in[2];
    const float* whhf = (const float*)d_in[3];
    const float* bihf = (const float*)d_in[4];
    const float* bhhf = (const float*)d_in[5];
    const float* wihb = (const float*)d_in[6];
    const float* whhb = (const float*)d_in[7];
    const float* bihb = (const float*)d_in[8];
    const float* bhhb = (const float*)d_in[9];
    const float* wout = (const float*)d_in[10];
    const float* bout = (const float*)d_in[11];
    float* out = (float*)d_out;

    cudaFuncSetAttribute(k4_lstm, cudaFuncAttributeMaxDynamicSharedMemorySize, K4_SMEM_BYTES);

    k1_seg <<<BATCH, 256>>>(x);
    k2_pool<<<dim3(NUTT, BATCH), 256>>>(x, emb);
    k3_gemm<<<dim3(MTOT / BM, (2 * G4) / BN), 256>>>(wihf, wihb, bihf, bhhf, bihb, bhhb);
    k4_lstm<<<2 * BATCH, 256, K4_SMEM_BYTES>>>(whhf, whhb);
    k5_head<<<MTOT / 8, 256>>>(wout, bout, out);
    k6_mask<<<(L_SEQ * BATCH) / 256, 256>>>(x, out);
}

// round 5
// speedup vs baseline: 1.3228x; 1.0845x over previous
#include <cuda_runtime.h>
#include <cuda_bf16.h>
#include <math.h>

#define L_SEQ   2048
#define BATCH   64
#define EMB     256
#define HID     128
#define G4      512
#define NUTT    128
#define SEP_TOK 50256
#define MTOT    (NUTT * BATCH)   // 8192

typedef unsigned long long u64;

// ---------------- f32x2 helpers (Blackwell packed fp32) ----------------
__device__ __forceinline__ u64 pack2(float lo, float hi) {
    u64 r; asm("mov.b64 %0, {%1, %2};" : "=l"(r) : "f"(lo), "f"(hi)); return r;
}
__device__ __forceinline__ u64 fma2(u64 a, u64 b, u64 c) {
    u64 d; asm("fma.rn.f32x2 %0, %1, %2, %3;" : "=l"(d) : "l"(a), "l"(b), "l"(c)); return d;
}
__device__ __forceinline__ float2 unpack2(u64 v) {
    float2 f; asm("mov.b64 {%0, %1}, %2;" : "=f"(f.x), "=f"(f.y) : "l"(v)); return f;
}

// ---------------- device scratch ----------------
__device__ int   g_seg[L_SEQ * BATCH];
__device__ int   g_ustart[(NUTT + 1) * BATCH];
__device__ float g_u[MTOT * EMB];
__device__ float g_xp[2ull * MTOT * G4];
__device__ float g_h[2ull * MTOT * HID];
__device__ int   g_umask[MTOT];

__device__ __forceinline__ float sig_fast(float x) {
    return __fdividef(1.0f, 1.0f + __expf(-x));
}
__device__ __forceinline__ float tanh_fast(float x) {
    float t = __expf(2.0f * x);
    return 1.0f - __fdividef(2.0f, t + 1.0f);
}

// ---------------- K1: segment ids + utterance starts ----------------
__global__ void k1_seg(const int* __restrict__ x) {
    int b = blockIdx.x, tid = threadIdx.x;
    __shared__ int cnt[256];
    for (int i = tid; i <= NUTT; i += 256) g_ustart[i * BATCH + b] = L_SEQ;
    int base = tid * 8;
    int loc[8]; int c = 0;
    #pragma unroll
    for (int k = 0; k < 8; k++) {
        loc[k] = (x[(base + k) * BATCH + b] == SEP_TOK) ? 1 : 0;
        c += loc[k];
    }
    cnt[tid] = c;
    __syncthreads();
    for (int off = 1; off < 256; off <<= 1) {
        int v = (tid >= off) ? cnt[tid - off] : 0;
        __syncthreads();
        cnt[tid] += v;
        __syncthreads();
    }
    int run = (tid > 0) ? cnt[tid - 1] : 0;
    #pragma unroll
    for (int k = 0; k < 8; k++) {
        int t = base + k;
        g_seg[t * BATCH + b] = run;
        if (loc[k]) {
            if (run + 1 <= NUTT) g_ustart[(run + 1) * BATCH + b] = t + 1;
            run++;
        }
    }
    if (tid == 0) g_ustart[b] = 0;
}

// ---------------- K2: ragged mean-pool ----------------
__global__ void k2_pool(const int* __restrict__ x, const float* __restrict__ emb) {
    int uu = blockIdx.x, b = blockIdx.y;
    __shared__ int rows[L_SEQ];
    __shared__ int se[2];
    if (threadIdx.x < 2)
        se[threadIdx.x] = g_ustart[(uu + threadIdx.x) * BATCH + b];
    __syncthreads();
    int s = se[0], e = se[1];
    for (int t = s + threadIdx.x; t < e; t += 256) rows[t - s] = x[t * BATCH + b];
    __syncthreads();
    int n = e - s;
    float sum = 0.f;
    for (int i = 0; i < n; i++)
        sum += emb[(size_t)rows[i] * EMB + threadIdx.x];
    g_u[((size_t)uu * BATCH + b) * EMB + threadIdx.x] = (n > 0) ? sum / (float)n : 0.f;
}

// ---------------- K3: xp = U @ Wcat^T + biases (fp32, f32x2 FFMA) ----------------
#define BM 128
#define BN 128
#define BKK 16
#define NKT (EMB / BKK)
__global__ void __launch_bounds__(256) k3_gemm(
    const float* __restrict__ wihf, const float* __restrict__ wihb,
    const float* __restrict__ bihf, const float* __restrict__ bhhf,
    const float* __restrict__ bihb, const float* __restrict__ bhhb) {
    __shared__ float As[2][BKK][BM + 4];
    __shared__ float Bs[2][BKK][BN + 4];
    int m0 = blockIdx.x * BM, n0 = blockIdx.y * BN;
    int tid = threadIdx.x;
    int tx = tid & 15, ty = tid >> 4;
    u64 acc2[8][4];
    #pragma unroll
    for (int i = 0; i < 8; i++)
        #pragma unroll
        for (int j = 0; j < 4; j++) acc2[i][j] = 0ull;

    int t2a = tid * 2, t2b = tid * 2 + 1;
    int ra = t2a >> 2, ca = (t2a & 3) * 4;
    int rb = t2b >> 2, cb = (t2b & 3) * 4;
    int na = n0 + ra, nb = n0 + rb;
    const float* bpa = (na < G4) ? &wihf[(size_t)na * EMB] : &wihb[(size_t)(na - G4) * EMB];
    const float* bpb = (nb < G4) ? &wihf[(size_t)nb * EMB] : &wihb[(size_t)(nb - G4) * EMB];
    const float* apa = &g_u[(size_t)(m0 + ra) * EMB];
    const float* apb = &g_u[(size_t)(m0 + rb) * EMB];

    float4 av0, av1, bv0, bv1;
    av0 = *(const float4*)&apa[ca];
    av1 = *(const float4*)&apb[cb];
    bv0 = *(const float4*)&bpa[ca];
    bv1 = *(const float4*)&bpb[cb];
    {
        As[0][ca + 0][ra] = av0.x; As[0][ca + 1][ra] = av0.y;
        As[0][ca + 2][ra] = av0.z; As[0][ca + 3][ra] = av0.w;
        As[0][cb + 0][rb] = av1.x; As[0][cb + 1][rb] = av1.y;
        As[0][cb + 2][rb] = av1.z; As[0][cb + 3][rb] = av1.w;
        Bs[0][ca + 0][ra] = bv0.x; Bs[0][ca + 1][ra] = bv0.y;
        Bs[0][ca + 2][ra] = bv0.z; Bs[0][ca + 3][ra] = bv0.w;
        Bs[0][cb + 0][rb] = bv1.x; Bs[0][cb + 1][rb] = bv1.y;
        Bs[0][cb + 2][rb] = bv1.z; Bs[0][cb + 3][rb] = bv1.w;
    }
    __syncthreads();

    #pragma unroll 1
    for (int kt = 0; kt < NKT; kt++) {
        int cur = kt & 1;
        if (kt + 1 < NKT) {
            int k0 = (kt + 1) * BKK;
            av0 = *(const float4*)&apa[k0 + ca];
            av1 = *(const float4*)&apb[k0 + cb];
            bv0 = *(const float4*)&bpa[k0 + ca];
            bv1 = *(const float4*)&bpb[k0 + cb];
        }
        #pragma unroll
        for (int kk = 0; kk < BKK; kk++) {
            float4 a0 = *(const float4*)&As[cur][kk][ty * 8];
            float4 a1 = *(const float4*)&As[cur][kk][ty * 8 + 4];
            float4 b0 = *(const float4*)&Bs[cur][kk][tx * 8];
            float4 b1 = *(const float4*)&Bs[cur][kk][tx * 8 + 4];
            u64 b2[4] = {pack2(b0.x, b0.y), pack2(b0.z, b0.w),
                         pack2(b1.x, b1.y), pack2(b1.z, b1.w)};
            float a[8] = {a0.x, a0.y, a0.z, a0.w, a1.x, a1.y, a1.z, a1.w};
            #pragma unroll
            for (int i = 0; i < 8; i++) {
                u64 a2 = pack2(a[i], a[i]);
                #pragma unroll
                for (int jp = 0; jp < 4; jp++)
                    acc2[i][jp] = fma2(a2, b2[jp], acc2[i][jp]);
            }
        }
        if (kt + 1 < NKT) {
            int nxt = 1 - cur;
            As[nxt][ca + 0][ra] = av0.x; As[nxt][ca + 1][ra] = av0.y;
            As[nxt][ca + 2][ra] = av0.z; As[nxt][ca + 3][ra] = av0.w;
            As[nxt][cb + 0][rb] = av1.x; As[nxt][cb + 1][rb] = av1.y;
            As[nxt][cb + 2][rb] = av1.z; As[nxt][cb + 3][rb] = av1.w;
            Bs[nxt][ca + 0][ra] = bv0.x; Bs[nxt][ca + 1][ra] = bv0.y;
            Bs[nxt][ca + 2][ra] = bv0.z; Bs[nxt][ca + 3][ra] = bv0.w;
            Bs[nxt][cb + 0][rb] = bv1.x; Bs[nxt][cb + 1][rb] = bv1.y;
            Bs[nxt][cb + 2][rb] = bv1.z; Bs[nxt][cb + 3][rb] = bv1.w;
            __syncthreads();
        }
    }
    #pragma unroll
    for (int i = 0; i < 8; i++) {
        int m = m0 + ty * 8 + i;
        #pragma unroll
        for (int jp = 0; jp < 4; jp++) {
            float2 v = unpack2(acc2[i][jp]);
            #pragma unroll
            for (int h = 0; h < 2; h++) {
                int n   = n0 + tx * 8 + 2 * jp + h;
                int dir = n >> 9;
                int gi  = n & (G4 - 1);
                float bias = dir ? (bihb[gi] + bhhb[gi]) : (bihf[gi] + bhhf[gi]);
                g_xp[((size_t)dir * MTOT + m) * G4 + gi] = (h ? v.y : v.x) + bias;
            }
        }
    }
}

// ---------------- K4: persistent BiLSTM (f32x2 matvec + fast activations) ----------------
// 128 blocks = (dir, batch), 256 threads, 1 CTA/SM.
// Thread tid owns gate rows: row tid (i/f) and row 256+tid (g/o).
//   wgop[64] u64 : full row 256+tid, j-pairs
//   wifp[32] u64 : j=0..63 of row tid, j-pairs
//   smem ws2     : j-pairs 32..63 (j=64..127) of rows 0..255, transposed
#define WS2_S  257                       // stride in u64
#define WS2_U64 (32 * WS2_S)             // 8224 u64 = 65792 B
#define K4_SMEM_BYTES (WS2_U64 * 8 + (512 + 128) * 4)

__global__ void __launch_bounds__(256, 1) k4_lstm(
    const float* __restrict__ whhf, const float* __restrict__ whhb) {
    extern __shared__ u64 smu[];
    u64*   ws2 = smu;
    float* gsm = (float*)(smu + WS2_U64);
    float* hsm = gsm + 512;

    int bi = blockIdx.x;
    int dir = bi >> 6, b = bi & 63;
    const float* whh = dir ? whhb : whhf;
    int tid = threadIdx.x;

    // smem: j-pairs 32..63 of rows 0..255 (i/f gates), transposed
    #pragma unroll
    for (int jp = 0; jp < 32; jp++)
        ws2[jp * WS2_S + tid] = *(const u64*)&whh[(size_t)tid * HID + 64 + 2 * jp];
    // registers
    u64 wgop[64];
    {
        const u64* wr = (const u64*)(whh + (size_t)(256 + tid) * HID);
        #pragma unroll
        for (int q = 0; q < 64; q++) wgop[q] = wr[q];
    }
    u64 wifp[32];
    {
        const u64* wr = (const u64*)(whh + (size_t)tid * HID);
        #pragma unroll
        for (int q = 0; q < 32; q++) wifp[q] = wr[q];
    }
    if (tid < HID) hsm[tid] = 0.f;
    float c = 0.f;
    __syncthreads();

    int t0 = dir ? (NUTT - 1) : 0;
    size_t base0 = ((size_t)dir * MTOT + (size_t)t0 * BATCH + b) * G4;
    float xpA = g_xp[base0 + tid];
    float xpB = g_xp[base0 + 256 + tid];
    float xpA_n = 0.f, xpB_n = 0.f;

    #pragma unroll 1
    for (int s = 0; s < NUTT; s++) {
        int t = dir ? (NUTT - 1 - s) : s;
        if (s + 1 < NUTT) {
            int tn = dir ? (NUTT - 2 - s) : (s + 1);
            size_t bn = ((size_t)dir * MTOT + (size_t)tn * BATCH + b) * G4;
            xpA_n = g_xp[bn + tid];
            xpB_n = g_xp[bn + 256 + tid];
        }

        u64 aA0 = 0ull, aA1 = 0ull, aB0 = 0ull, aB1 = 0ull;
        // j = 0..63 : i/f weights from regs
        #pragma unroll
        for (int u = 0; u < 16; u++) {
            float4 h4 = *(const float4*)&hsm[4 * u];
            u64 hx = pack2(h4.x, h4.y);
            u64 hy = pack2(h4.z, h4.w);
            aA0 = fma2(wifp[2 * u],     hx, aA0);
            aA1 = fma2(wifp[2 * u + 1], hy, aA1);
            aB0 = fma2(wgop[2 * u],     hx, aB0);
            aB1 = fma2(wgop[2 * u + 1], hy, aB1);
        }
        // j = 64..127 : i/f weights from smem
        #pragma unroll
        for (int u = 0; u < 16; u++) {
            float4 h4 = *(const float4*)&hsm[64 + 4 * u];
            u64 hx = pack2(h4.x, h4.y);
            u64 hy = pack2(h4.z, h4.w);
            aA0 = fma2(ws2[(2 * u)     * WS2_S + tid], hx, aA0);
            aA1 = fma2(ws2[(2 * u + 1) * WS2_S + tid], hy, aA1);
            aB0 = fma2(wgop[32 + 2 * u],     hx, aB0);
            aB1 = fma2(wgop[32 + 2 * u + 1], hy, aB1);
        }
        float2 vA0 = unpack2(aA0), vA1 = unpack2(aA1);
        float2 vB0 = unpack2(aB0), vB1 = unpack2(aB1);
        gsm[tid]       = (vA0.x + vA0.y) + (vA1.x + vA1.y) + xpA;
        gsm[256 + tid] = (vB0.x + vB0.y) + (vB1.x + vB1.y) + xpB;
        __syncthreads();
        if (tid < HID) {
            float gi = gsm[tid], gf = gsm[HID + tid];
            float gg = gsm[256 + tid], go = gsm[384 + tid];
            c = sig_fast(gf) * c + sig_fast(gi) * tanh_fast(gg);
            float h = sig_fast(go) * tanh_fast(c);
            hsm[tid] = h;
            g_h[(((size_t)dir * NUTT + t) * BATCH + b) * HID + tid] = h;
        }
        xpA = xpA_n;
        xpB = xpB_n;
        __syncthreads();
    }
}

// ---------------- K5: head (warp per (t,b)) ----------------
__global__ void k5_head(const float* __restrict__ wout, const float* __restrict__ bout,
                        float* __restrict__ out) {
    int w = threadIdx.x >> 5, lane = threadIdx.x & 31;
    int idx = blockIdx.x * 8 + w;
    if (idx >= MTOT) return;
    int t = idx >> 6, b = idx & 63;
    const float* hf = &g_h[(((size_t)0 * NUTT + t) * BATCH + b) * HID];
    const float* hb = &g_h[(((size_t)1 * NUTT + t) * BATCH + b) * HID];
    float l0 = 0.f, l1 = 0.f;
    #pragma unroll
    for (int q = 0; q < 4; q++) {
        int e = q * 32 + lane;
        float vf = hf[e], vb = hb[e];
        l0 += vf * wout[e] + vb * wout[HID + e];
        l1 += vf * wout[EMB + e] + vb * wout[EMB + HID + e];
    }
    #pragma unroll
    for (int off = 16; off > 0; off >>= 1) {
        l0 += __shfl_xor_sync(0xFFFFFFFFu, l0, off);
        l1 += __shfl_xor_sync(0xFFFFFFFFu, l1, off);
    }
    if (lane == 0) {
        l0 += bout[0]; l1 += bout[1];
        float m  = fmaxf(l0, l1);
        float e0 = expf(l0 - m), e1 = expf(l1 - m);
        float s  = e0 + e1;
        float p0 = e0 / s, p1 = e1 / s;
        int am = (l1 > l0) ? 1 : 0;
        out[idx * 2 + 0]         = l0;
        out[idx * 2 + 1]         = l1;
        out[16384 + idx * 2 + 0] = p0;
        out[16384 + idx * 2 + 1] = p1;
        out[32768 + idx]         = am ? p1 : p0;
        out[40960 + idx]         = (float)am;
        g_umask[idx]             = am;
    }
}

// ---------------- K6: expand mask to tokens ----------------
__global__ void k6_mask(const int* __restrict__ x, float* __restrict__ out) {
    int i = blockIdx.x * blockDim.x + threadIdx.x;
    if (i >= L_SEQ * BATCH) return;
    int b   = i & 63;
    int seg = g_seg[i];
    int m   = g_umask[seg * BATCH + b];
    out[49152 + i] = m ? (float)x[i] : 0.0f;
}

extern "C" void kernel_launch(void* const* d_in, const int* in_sizes, int n_in,
                              void* d_out, int out_size) {
    const int*   x    = (const int*)d_in[0];
    const float* emb  = (const float*)d_in[1];
    const float* wihf = (const float*)d_in[2];
    const float* whhf = (const float*)d_in[3];
    const float* bihf = (const float*)d_in[4];
    const float* bhhf = (const float*)d_in[5];
    const float* wihb = (const float*)d_in[6];
    const float* whhb = (const float*)d_in[7];
    const float* bihb = (const float*)d_in[8];
    const float* bhhb = (const float*)d_in[9];
    const float* wout = (const float*)d_in[10];
    const float* bout = (const float*)d_in[11];
    float* out = (float*)d_out;

    cudaFuncSetAttribute(k4_lstm, cudaFuncAttributeMaxDynamicSharedMemorySize, K4_SMEM_BYTES);

    k1_seg <<<BATCH, 256>>>(x);
    k2_pool<<<dim3(NUTT, BATCH), 256>>>(x, emb);
    k3_gemm<<<dim3(MTOT / BM, (2 * G4) / BN), 256>>>(wihf, wihb, bihf, bhhf, bihb, bhhb);
    k4_lstm<<<2 * BATCH, 256, K4_SMEM_BYTES>>>(whhf, whhb);
    k5_head<<<MTOT / 8, 256>>>(wout, bout, out);
    k6_mask<<<(L_SEQ * BATCH) / 256, 256>>>(x, out);
}